// round 10
// baseline (speedup 1.0000x reference)
#include <cuda_runtime.h>
#include <cuda_fp16.h>
#include <math.h>
#include <mma.h>

using namespace nvcuda;

#define NN 100000
#define NPAD 100032            /* 1563 * 64 */
#define EE 1600000
#define GG 256
#define NB_SCAN 98             /* ceil(NN/1024) */

// ---------------- scratch (device globals; no allocation allowed) ----------
__device__ float  g_x[NPAD * 128];
__device__ float  g_y[NPAD * 128];
__device__ float  g_h[NPAD * 128];
__device__ __half g_hh[NPAD * 128];     // half gather array: GCN h
__device__ __half g_hgh[NPAD * 128];    // half gather array: GAT hg
__device__ __half g_xh[NPAD * 64];      // half gather array: layer0 GAT output
__device__ int    g_cnt[NN];
__device__ int    g_offs[NN];
__device__ int    g_cursor[NN];
__device__ int    g_csrc[EE];
__device__ float  g_ew[EE];             // per-edge GCN norm dis[src]*dis[dst]
__device__ float  g_dis[NN];
__device__ float  g_an_src[NN * 4];
__device__ float  g_an_dst[NN * 4];
__device__ float  g_bnsum[4][128];
__device__ float  g_bnsq[4][128];
__device__ int    g_bsum[128];
__device__ float  g_pool[GG * 64];
__device__ float  g_pcnt[GG];

__device__ __forceinline__ float lrelu(float v) { return v > 0.f ? v : 0.2f * v; }

__device__ __forceinline__ void bn_affine(int layer, int c, const float* g, const float* b,
                                          float& scv, float& shf) {
    float mean = g_bnsum[layer][c] * (1.f / NN);
    float var = g_bnsq[layer][c] * (1.f / NN) - mean * mean;
    float istd = rsqrtf(var + 1e-5f);
    scv = g[c] * istd;
    shf = b[c] - mean * scv;
}

// ---------------- init / CSR build ----------------------------------------
__global__ void zero_init() {
    int i = blockIdx.x * blockDim.x + threadIdx.x;
    int stride = gridDim.x * blockDim.x;
    for (int t = i; t < NN; t += stride) { g_cnt[t] = 0; g_cursor[t] = 0; }
    for (int t = i; t < GG * 64; t += stride) g_pool[t] = 0.f;
    for (int t = i; t < GG; t += stride) g_pcnt[t] = 0.f;
    for (int t = i; t < 4 * 128; t += stride) { (&g_bnsum[0][0])[t] = 0.f; (&g_bnsq[0][0])[t] = 0.f; }
}

__global__ void hist_k(const int* __restrict__ col, const int* __restrict__ batch) {
    int i = blockIdx.x * blockDim.x + threadIdx.x;
    int stride = gridDim.x * blockDim.x;
    for (int e = i; e < EE; e += stride)
        atomicAdd(&g_cnt[col[e]], 1);
    for (int t = i; t < NN; t += stride)
        atomicAdd(&g_pcnt[batch[t]], 1.f);
}

__global__ void scan1() {
    __shared__ int s[1024];
    int t = threadIdx.x;
    int gi = blockIdx.x * 1024 + t;
    int v = (gi < NN) ? g_cnt[gi] : 0;
    s[t] = v;
    for (int off = 1; off < 1024; off <<= 1) {
        __syncthreads();
        int u = (t >= off) ? s[t - off] : 0;
        __syncthreads();
        s[t] += u;
    }
    if (gi < NN) g_offs[gi] = s[t] - v;
    if (t == 1023) g_bsum[blockIdx.x] = s[1023];
}

__global__ void scan3_dis() {
    __shared__ int sbase;
    int t = threadIdx.x;
    if (t == 0) sbase = 0;
    __syncthreads();
    int p = (t < blockIdx.x) ? g_bsum[t] : 0;
#pragma unroll
    for (int off = 16; off > 0; off >>= 1)
        p += __shfl_xor_sync(0xffffffffu, p, off);
    if ((t & 31) == 0 && p) atomicAdd(&sbase, p);
    __syncthreads();
    int gi = blockIdx.x * 1024 + t;
    if (gi < NN) {
        g_offs[gi] += sbase;
        g_dis[gi] = rsqrtf((float)(g_cnt[gi] + 1));
    }
}

__global__ void scatter_k(const int* __restrict__ row, const int* __restrict__ col) {
    int i = blockIdx.x * blockDim.x + threadIdx.x;
    for (int e = i; e < EE; e += gridDim.x * blockDim.x) {
        int c = col[e];
        int r = row[e];
        int pos = g_offs[c] + atomicAdd(&g_cursor[c], 1);
        g_csrc[pos] = r;
        g_ew[pos] = g_dis[r] * g_dis[c];
    }
}

// ---------------- GEMM: 3xTF32 WMMA, pre-split tiles -----------------------
#define BM 64
#define BN 64
#define BK 32

template <int TRANS, int EPI>
__global__ void gemm_tf32(const float* __restrict__ A, const float* __restrict__ W,
                          float* __restrict__ out, __half* __restrict__ out_h,
                          int n, int din, int dout,
                          const float* __restrict__ bng, const float* __restrict__ bnb,
                          int alayer,
                          const float* __restrict__ bias, int slayer,
                          const float* __restrict__ av_src, const float* __restrict__ av_dst) {
    __shared__ float As[2][BM][BK + 8];
    __shared__ float Bs[2][BK][BN + 8];
    __shared__ float sc_s[128], sh_s[128];
    int tid = threadIdx.x;
    int warp = tid >> 5;
    int wr = warp >> 1;
    int wc = warp & 1;
    int row0 = blockIdx.x * BM;
    int col0 = blockIdx.y * BN;

    if (TRANS > 0) {
        for (int t = tid; t < din; t += 256) {
            float scv, shf;
            bn_affine(alayer, t, bng, bnb, scv, shf);
            sc_s[t] = scv;
            sh_s[t] = shf;
        }
        __syncthreads();
    }

    wmma::fragment<wmma::accumulator, 16, 16, 8, float> acc[2];
    wmma::fill_fragment(acc[0], 0.f);
    wmma::fill_fragment(acc[1], 0.f);

    for (int k0 = 0; k0 < din; k0 += BK) {
#pragma unroll
        for (int v = tid; v < BM * 8; v += 256) {
            int r = v >> 3;
            int kk = (v & 7) * 4;
            float4 val = make_float4(0.f, 0.f, 0.f, 0.f);
            int grow = row0 + r, gk = k0 + kk;
            if (grow < n && gk < din) {
                val = *(const float4*)(A + (size_t)grow * din + gk);
                if (TRANS > 0) {
                    val.x = val.x * sc_s[gk] + sh_s[gk];
                    val.y = val.y * sc_s[gk + 1] + sh_s[gk + 1];
                    val.z = val.z * sc_s[gk + 2] + sh_s[gk + 2];
                    val.w = val.w * sc_s[gk + 3] + sh_s[gk + 3];
                    if (TRANS == 2) {
                        val.x = lrelu(val.x); val.y = lrelu(val.y);
                        val.z = lrelu(val.z); val.w = lrelu(val.w);
                    }
                }
            }
            float4 hi, lo;
            hi.x = wmma::__float_to_tf32(val.x); lo.x = wmma::__float_to_tf32(val.x - hi.x);
            hi.y = wmma::__float_to_tf32(val.y); lo.y = wmma::__float_to_tf32(val.y - hi.y);
            hi.z = wmma::__float_to_tf32(val.z); lo.z = wmma::__float_to_tf32(val.z - hi.z);
            hi.w = wmma::__float_to_tf32(val.w); lo.w = wmma::__float_to_tf32(val.w - hi.w);
            *(float4*)&As[0][r][kk] = hi;
            *(float4*)&As[1][r][kk] = lo;
        }
#pragma unroll
        for (int v = tid; v < BK * 16; v += 256) {
            int kk = v >> 4;
            int cc = (v & 15) * 4;
            float4 val = make_float4(0.f, 0.f, 0.f, 0.f);
            int gk = k0 + kk;
            if (gk < din)
                val = *(const float4*)(W + (size_t)gk * dout + col0 + cc);
            float4 hi, lo;
            hi.x = wmma::__float_to_tf32(val.x); lo.x = wmma::__float_to_tf32(val.x - hi.x);
            hi.y = wmma::__float_to_tf32(val.y); lo.y = wmma::__float_to_tf32(val.y - hi.y);
            hi.z = wmma::__float_to_tf32(val.z); lo.z = wmma::__float_to_tf32(val.z - hi.z);
            hi.w = wmma::__float_to_tf32(val.w); lo.w = wmma::__float_to_tf32(val.w - hi.w);
            *(float4*)&Bs[0][kk][cc] = hi;
            *(float4*)&Bs[1][kk][cc] = lo;
        }
        __syncthreads();

#pragma unroll
        for (int ks = 0; ks < BK; ks += 8) {
            wmma::fragment<wmma::matrix_a, 16, 16, 8, wmma::precision::tf32, wmma::row_major> a_hi, a_lo;
            wmma::load_matrix_sync(a_hi, &As[0][wr * 16][ks], BK + 8);
            wmma::load_matrix_sync(a_lo, &As[1][wr * 16][ks], BK + 8);
#pragma unroll
            for (int c = 0; c < 2; c++) {
                wmma::fragment<wmma::matrix_b, 16, 16, 8, wmma::precision::tf32, wmma::row_major> b_hi, b_lo;
                wmma::load_matrix_sync(b_hi, &Bs[0][ks][wc * 32 + c * 16], BN + 8);
                wmma::load_matrix_sync(b_lo, &Bs[1][ks][wc * 32 + c * 16], BN + 8);
                wmma::mma_sync(acc[c], a_hi, b_hi, acc[c]);
                wmma::mma_sync(acc[c], a_lo, b_hi, acc[c]);
                wmma::mma_sync(acc[c], a_hi, b_lo, acc[c]);
            }
        }
        __syncthreads();
    }

    float* buf = &As[0][0][0];
    const int LDB = 72;
#pragma unroll
    for (int c = 0; c < 2; c++)
        wmma::store_matrix_sync(buf + (wr * 16) * LDB + wc * 32 + c * 16,
                                acc[c], LDB, wmma::mem_row_major);
    __syncthreads();

    if (EPI == 1) {
        int col = tid & 63;
        int part = tid >> 6;
        int gcol = col0 + col;
        float bv = bias[gcol];
        float s = 0.f, q = 0.f;
#pragma unroll
        for (int r = part * 16; r < part * 16 + 16; r++) {
            float v = buf[r * LDB + col] + bv;
            int grow = row0 + r;
            out[(size_t)grow * dout + gcol] = v;
            if (grow < n) { s += v; q += v * v; }
        }
        __shared__ float cS[64], cQ[64];
        if (tid < 64) { cS[tid] = 0.f; cQ[tid] = 0.f; }
        __syncthreads();
        atomicAdd(&cS[col], s);
        atomicAdd(&cQ[col], q);
        __syncthreads();
        if (tid < 64) {
            atomicAdd(&g_bnsum[slayer][col0 + tid], cS[tid]);
            atomicAdd(&g_bnsq[slayer][col0 + tid], cQ[tid]);
        }
    } else {
        __half2* oh = (__half2*)out_h;
        int d2 = dout >> 1;
#pragma unroll
        for (int idx = tid; idx < 64 * 32; idx += 256) {
            int r = idx >> 5, c2 = idx & 31;
            float v0 = buf[r * LDB + 2 * c2];
            float v1 = buf[r * LDB + 2 * c2 + 1];
            oh[(size_t)(row0 + r) * d2 + (col0 >> 1) + c2] = __floats2half2_rn(v0, v1);
        }
        if (EPI == 2) {
            int row = tid & 63;
            int part = tid >> 6;
            int c0 = part * 16;
            int C = dout >> 2;
            int hh = (col0 + c0) / C;
            float s1 = 0.f, s2 = 0.f;
#pragma unroll
            for (int c = c0; c < c0 + 16; c++) {
                float v = buf[row * LDB + c];
                s1 += v * av_src[col0 + c];
                s2 += v * av_dst[col0 + c];
            }
            __shared__ float sA[64][4], sD[64][4];
            sA[tid >> 2][tid & 3] = 0.f;
            sD[tid >> 2][tid & 3] = 0.f;
            __syncthreads();
            atomicAdd(&sA[row][hh], s1);
            atomicAdd(&sD[row][hh], s2);
            __syncthreads();
            int hlo = col0 / C;
            int hcnt = 64 / C;
            if (tid < 64 * hcnt) {
                int r = tid / hcnt, k = tid % hcnt;
                int grow = row0 + r;
                if (grow < n) {
                    g_an_src[grow * 4 + hlo + k] = sA[r][hlo + k];
                    g_an_dst[grow * 4 + hlo + k] = sD[r][hlo + k];
                }
            }
        }
    }
}

// ---------------- pre-aggregation @16: warp/node, half-warp/edge ------------
__global__ void pre_agg16_w(const float* __restrict__ x, float* __restrict__ z) {
    int gw = (blockIdx.x * blockDim.x + threadIdx.x) >> 5;
    if (gw >= NN) return;
    int i = gw;
    int lane = threadIdx.x & 31;
    int half = lane >> 4;
    int col = lane & 15;
    float di = g_dis[i];
    float acc = (half == 0) ? x[(size_t)i * 16 + col] * di * di : 0.f;
    int s = g_offs[i], end = s + g_cnt[i];
    int e = s + half;
    for (; e + 2 < end; e += 4) {
        int j0 = g_csrc[e], j1 = g_csrc[e + 2];
        float w0 = g_ew[e], w1 = g_ew[e + 2];
        acc += x[(size_t)j0 * 16 + col] * w0 + x[(size_t)j1 * 16 + col] * w1;
    }
    if (e < end)
        acc += x[(size_t)g_csrc[e] * 16 + col] * g_ew[e];
    acc += __shfl_xor_sync(0xffffffffu, acc, 16);
    if (half == 0)
        z[(size_t)i * 16 + col] = acc;
}

// ---------------- pre-agg @64 (half input), warp/node -----------------------
__global__ void pre_agg64_h(const __half2* __restrict__ x2, float* __restrict__ z) {
    int gw = (blockIdx.x * blockDim.x + threadIdx.x) >> 5;
    int lane = threadIdx.x & 31;
    if (gw >= NN) return;
    int i = gw;
    float di = g_dis[i], ws = di * di;
    float2 hv = __half22float2(x2[(size_t)i * 32 + lane]);
    float a0 = hv.x * ws, a1 = hv.y * ws;
    int e = g_offs[i], end = e + g_cnt[i];
    for (; e + 3 < end; e += 4) {
        int j0 = g_csrc[e], j1 = g_csrc[e + 1], j2 = g_csrc[e + 2], j3 = g_csrc[e + 3];
        float w0 = g_ew[e], w1 = g_ew[e + 1], w2 = g_ew[e + 2], w3 = g_ew[e + 3];
        float2 v0 = __half22float2(x2[(size_t)j0 * 32 + lane]);
        float2 v1 = __half22float2(x2[(size_t)j1 * 32 + lane]);
        float2 v2 = __half22float2(x2[(size_t)j2 * 32 + lane]);
        float2 v3 = __half22float2(x2[(size_t)j3 * 32 + lane]);
        a0 += v0.x * w0 + v1.x * w1 + v2.x * w2 + v3.x * w3;
        a1 += v0.y * w0 + v1.y * w1 + v2.y * w2 + v3.y * w3;
    }
    for (; e < end; e++) {
        int j = g_csrc[e];
        float w = g_ew[e];
        float2 v = __half22float2(x2[(size_t)j * 32 + lane]);
        a0 += v.x * w;
        a1 += v.y * w;
    }
    *(float2*)&z[(size_t)i * 64 + 2 * lane] = make_float2(a0, a1);
}

// ---------------- GCN post-agg @128: 2 warps/node (64 cols each) + stats ----
__global__ void gcn_agg128_2w(const __half2* __restrict__ h2, const float* __restrict__ bias,
                              float* __restrict__ y, int layer) {
    __shared__ float sS[128], sQ[128];
    int tid = threadIdx.x;
    for (int t = tid; t < 128; t += blockDim.x) { sS[t] = 0.f; sQ[t] = 0.f; }
    __syncthreads();
    int lane = tid & 31;
    int gw = (blockIdx.x * blockDim.x + tid) >> 5;
    if (gw >= 2 * NN) { __syncthreads(); return; }
    int i = gw >> 1;
    int chunk = gw & 1;
    int col = chunk * 64 + 2 * lane;
    size_t coff = (size_t)chunk * 32 + lane;     // half2 offset within 128-dim row
    float b0 = bias[col], b1 = bias[col + 1];
    float di = g_dis[i];
    float ws = di * di;
    float2 hv = __half22float2(h2[(size_t)i * 64 + coff]);
    float a0 = hv.x * ws, a1 = hv.y * ws;
    int e = g_offs[i];
    int end = e + g_cnt[i];
    for (; e + 3 < end; e += 4) {
        int j0 = g_csrc[e], j1 = g_csrc[e + 1], j2 = g_csrc[e + 2], j3 = g_csrc[e + 3];
        float w0 = g_ew[e], w1 = g_ew[e + 1], w2 = g_ew[e + 2], w3 = g_ew[e + 3];
        float2 v0 = __half22float2(h2[(size_t)j0 * 64 + coff]);
        float2 v1 = __half22float2(h2[(size_t)j1 * 64 + coff]);
        float2 v2 = __half22float2(h2[(size_t)j2 * 64 + coff]);
        float2 v3 = __half22float2(h2[(size_t)j3 * 64 + coff]);
        a0 += v0.x * w0 + v1.x * w1 + v2.x * w2 + v3.x * w3;
        a1 += v0.y * w0 + v1.y * w1 + v2.y * w2 + v3.y * w3;
    }
    for (; e < end; e++) {
        int j = g_csrc[e];
        float w = g_ew[e];
        float2 v = __half22float2(h2[(size_t)j * 64 + coff]);
        a0 += v.x * w;
        a1 += v.y * w;
    }
    float v0 = a0 + b0;
    float v1 = a1 + b1;
    *(float2*)&y[(size_t)i * 128 + col] = make_float2(v0, v1);
    atomicAdd(&sS[col], v0);
    atomicAdd(&sQ[col], v0 * v0);
    atomicAdd(&sS[col + 1], v1);
    atomicAdd(&sQ[col + 1], v1 * v1);
    __syncthreads();
    for (int t = tid; t < 128; t += blockDim.x) {
        atomicAdd(&g_bnsum[layer][t], sS[t]);
        atomicAdd(&g_bnsq[layer][t], sQ[t]);
    }
}

// ---------------- GCN post-agg @64 fused with pooling + stats ---------------
__global__ void gcn_pool_h(const __half2* __restrict__ h2, const float* __restrict__ bias,
                           const int* __restrict__ batch, int layer) {
    __shared__ float sS[64], sQ[64];
    int tid = threadIdx.x;
    for (int t = tid; t < 64; t += blockDim.x) { sS[t] = 0.f; sQ[t] = 0.f; }
    __syncthreads();
    int lane = tid & 31;
    int gw = (blockIdx.x * blockDim.x + tid) >> 5;
    int nw = (gridDim.x * blockDim.x) >> 5;
    int col = 2 * lane;
    float b0 = bias[col], b1 = bias[col + 1];
    float s0 = 0.f, s1 = 0.f, q0 = 0.f, q1 = 0.f;

    for (int i = gw; i < NN; i += nw) {
        float di = g_dis[i];
        float ws = di * di;
        float2 hv = __half22float2(h2[(size_t)i * 32 + lane]);
        float a0 = hv.x * ws, a1 = hv.y * ws;
        int e = g_offs[i];
        int end = e + g_cnt[i];
        for (; e + 3 < end; e += 4) {
            int j0 = g_csrc[e], j1 = g_csrc[e + 1], j2 = g_csrc[e + 2], j3 = g_csrc[e + 3];
            float w0 = g_ew[e], w1 = g_ew[e + 1], w2 = g_ew[e + 2], w3 = g_ew[e + 3];
            float2 v0 = __half22float2(h2[(size_t)j0 * 32 + lane]);
            float2 v1 = __half22float2(h2[(size_t)j1 * 32 + lane]);
            float2 v2 = __half22float2(h2[(size_t)j2 * 32 + lane]);
            float2 v3 = __half22float2(h2[(size_t)j3 * 32 + lane]);
            a0 += v0.x * w0 + v1.x * w1 + v2.x * w2 + v3.x * w3;
            a1 += v0.y * w0 + v1.y * w1 + v2.y * w2 + v3.y * w3;
        }
        for (; e < end; e++) {
            int j = g_csrc[e];
            float w = g_ew[e];
            float2 v = __half22float2(h2[(size_t)j * 32 + lane]);
            a0 += v.x * w;
            a1 += v.y * w;
        }
        float v0 = a0 + b0;
        float v1 = a1 + b1;
        int gph = batch[i] * 64 + col;
        atomicAdd(&g_pool[gph], v0);
        atomicAdd(&g_pool[gph + 1], v1);
        s0 += v0; q0 += v0 * v0;
        s1 += v1; q1 += v1 * v1;
    }
    atomicAdd(&sS[col], s0);
    atomicAdd(&sQ[col], q0);
    atomicAdd(&sS[col + 1], s1);
    atomicAdd(&sQ[col + 1], q1);
    __syncthreads();
    for (int t = tid; t < 64; t += blockDim.x) {
        atomicAdd(&g_bnsum[layer][t], sS[t]);
        atomicAdd(&g_bnsq[layer][t], sQ[t]);
    }
}

// ---------------- GAT @64 (layer 0): warp/node, lane-parallel logits --------
__global__ void gat_agg64_h(const __half2* __restrict__ hg2, const float* __restrict__ yres,
                            const float* __restrict__ bias, __half2* __restrict__ xout_h,
                            const float* __restrict__ bng, const float* __restrict__ bnb,
                            int layer) {
    __shared__ int    sj[8][32];
    __shared__ float4 sq[8][32];
    int gw = (blockIdx.x * blockDim.x + threadIdx.x) >> 5;
    int lane = threadIdx.x & 31;
    int w = threadIdx.x >> 5;
    if (gw >= NN) return;
    int i = gw;
    float4 asi = *(const float4*)&g_an_src[i * 4];
    float4 adi = *(const float4*)&g_an_dst[i * 4];
    float p0 = __expf(lrelu(asi.x + adi.x));
    float p1 = __expf(lrelu(asi.y + adi.y));
    float p2 = __expf(lrelu(asi.z + adi.z));
    float p3 = __expf(lrelu(asi.w + adi.w));
    int col = 2 * lane;
    int hh = col >> 4;                 // C=16 cols per head
    float psel = hh == 0 ? p0 : hh == 1 ? p1 : hh == 2 ? p2 : p3;
    float2 hv = __half22float2(hg2[(size_t)i * 32 + lane]);
    float a0 = hv.x * psel, a1 = hv.y * psel;
    float d0 = 0.f, d1 = 0.f, d2 = 0.f, d3 = 0.f;
    int s = g_offs[i], end = s + g_cnt[i];
    for (int base = s; base < end; base += 32) {
        int e = base + lane;
        float4 qv = make_float4(0.f, 0.f, 0.f, 0.f);
        int j = 0;
        if (e < end) {
            j = g_csrc[e];
            float4 aj = *(const float4*)&g_an_src[j * 4];
            qv.x = __expf(lrelu(aj.x + adi.x));
            qv.y = __expf(lrelu(aj.y + adi.y));
            qv.z = __expf(lrelu(aj.z + adi.z));
            qv.w = __expf(lrelu(aj.w + adi.w));
            d0 += qv.x; d1 += qv.y; d2 += qv.z; d3 += qv.w;
        }
        sj[w][lane] = j;
        sq[w][lane] = qv;
        __syncwarp();
        int m = min(32, end - base);
        int k = 0;
        for (; k + 1 < m; k += 2) {
            int j0 = sj[w][k], j1 = sj[w][k + 1];
            float qa = ((const float*)&sq[w][k])[hh];
            float qb = ((const float*)&sq[w][k + 1])[hh];
            float2 v0 = __half22float2(hg2[(size_t)j0 * 32 + lane]);
            float2 v1 = __half22float2(hg2[(size_t)j1 * 32 + lane]);
            a0 += v0.x * qa + v1.x * qb;
            a1 += v0.y * qa + v1.y * qb;
        }
        if (k < m) {
            int j0 = sj[w][k];
            float qa = ((const float*)&sq[w][k])[hh];
            float2 v0 = __half22float2(hg2[(size_t)j0 * 32 + lane]);
            a0 += v0.x * qa;
            a1 += v0.y * qa;
        }
        __syncwarp();
    }
#pragma unroll
    for (int off = 16; off > 0; off >>= 1) {
        d0 += __shfl_xor_sync(0xffffffffu, d0, off);
        d1 += __shfl_xor_sync(0xffffffffu, d1, off);
        d2 += __shfl_xor_sync(0xffffffffu, d2, off);
        d3 += __shfl_xor_sync(0xffffffffu, d3, off);
    }
    d0 += p0; d1 += p1; d2 += p2; d3 += p3;
    float d = hh == 0 ? d0 : hh == 1 ? d1 : hh == 2 ? d2 : d3;
    float sc0, sf0, sc1, sf1;
    bn_affine(layer, col, bng, bnb, sc0, sf0);
    bn_affine(layer, col + 1, bng, bnb, sc1, sf1);
    float2 rv = *(const float2*)&yres[(size_t)i * 64 + col];
    float v0 = lrelu(a0 / d + bias[col] + rv.x * sc0 + sf0);
    float v1 = lrelu(a1 / d + bias[col + 1] + rv.y * sc1 + sf1);
    xout_h[(size_t)i * 32 + lane] = __floats2half2_rn(v0, v1);
}

// ---------------- GAT @128 (layer 2): 2 warps/node, lane-parallel logits ----
__global__ void gat_agg128_2w(const __half2* __restrict__ hg2, const float* __restrict__ yres,
                              const float* __restrict__ bias, float* __restrict__ xout,
                              const float* __restrict__ bng, const float* __restrict__ bnb,
                              int layer) {
    __shared__ int    sj[8][32];
    __shared__ float2 sq[8][32];
    int gw = (blockIdx.x * blockDim.x + threadIdx.x) >> 5;
    int lane = threadIdx.x & 31;
    int w = threadIdx.x >> 5;
    if (gw >= 2 * NN) return;
    int i = gw >> 1;
    int chunk = gw & 1;                 // chunk 0 -> heads 0,1 ; chunk 1 -> heads 2,3
    int col = chunk * 64 + 2 * lane;
    size_t coff = (size_t)chunk * 32 + lane;
    float asA = g_an_src[i * 4 + 2 * chunk];
    float asB = g_an_src[i * 4 + 2 * chunk + 1];
    float adA = g_an_dst[i * 4 + 2 * chunk];
    float adB = g_an_dst[i * 4 + 2 * chunk + 1];
    float pA = __expf(lrelu(asA + adA));
    float pB = __expf(lrelu(asB + adB));
    int hsel = lane >> 4;               // C=32 cols/head: lanes 0-15 head A, 16-31 head B
    float psel = hsel == 0 ? pA : pB;
    float2 hv = __half22float2(hg2[(size_t)i * 64 + coff]);
    float a0 = hv.x * psel, a1 = hv.y * psel;
    float dA = 0.f, dB = 0.f;
    int s = g_offs[i], end = s + g_cnt[i];
    for (int base = s; base < end; base += 32) {
        int e = base + lane;
        float2 qv = make_float2(0.f, 0.f);
        int j = 0;
        if (e < end) {
            j = g_csrc[e];
            float2 aj = *(const float2*)&g_an_src[j * 4 + 2 * chunk];
            qv.x = __expf(lrelu(aj.x + adA));
            qv.y = __expf(lrelu(aj.y + adB));
            dA += qv.x; dB += qv.y;
        }
        sj[w][lane] = j;
        sq[w][lane] = qv;
        __syncwarp();
        int m = min(32, end - base);
        int k = 0;
        for (; k + 1 < m; k += 2) {
            int j0 = sj[w][k], j1 = sj[w][k + 1];
            float qa = hsel == 0 ? sq[w][k].x : sq[w][k].y;
            float qb = hsel == 0 ? sq[w][k + 1].x : sq[w][k + 1].y;
            float2 v0 = __half22float2(hg2[(size_t)j0 * 64 + coff]);
            float2 v1 = __half22float2(hg2[(size_t)j1 * 64 + coff]);
            a0 += v0.x * qa + v1.x * qb;
            a1 += v0.y * qa + v1.y * qb;
        }
        if (k < m) {
            int j0 = sj[w][k];
            float qa = hsel == 0 ? sq[w][k].x : sq[w][k].y;
            float2 v0 = __half22float2(hg2[(size_t)j0 * 64 + coff]);
            a0 += v0.x * qa;
            a1 += v0.y * qa;
        }
        __syncwarp();
    }
#pragma unroll
    for (int off = 16; off > 0; off >>= 1) {
        dA += __shfl_xor_sync(0xffffffffu, dA, off);
        dB += __shfl_xor_sync(0xffffffffu, dB, off);
    }
    dA += pA; dB += pB;
    float d = hsel == 0 ? dA : dB;
    float sc0, sf0, sc1, sf1;
    bn_affine(layer, col, bng, bnb, sc0, sf0);
    bn_affine(layer, col + 1, bng, bnb, sc1, sf1);
    float2 rv = *(const float2*)&yres[(size_t)i * 128 + col];
    float v0 = lrelu(a0 / d + bias[col] + rv.x * sc0 + sf0);
    float v1 = lrelu(a1 / d + bias[col + 1] + rv.y * sc1 + sf1);
    *(float2*)&xout[(size_t)i * 128 + col] = make_float2(v0, v1);
}

// ---------------- pooling finalize ------------------------------------------
__global__ void pool_fin(float* __restrict__ out,
                         const float* __restrict__ bng, const float* __restrict__ bnb) {
    int i = blockIdx.x * blockDim.x + threadIdx.x;
    if (i < GG * 64) {
        int g = i >> 6, c = i & 63;
        float scv, shf;
        bn_affine(3, c, bng, bnb, scv, shf);
        float cnt = g_pcnt[g];
        out[i] = (g_pool[i] * scv + shf * cnt) / fmaxf(cnt, 1.f);
    }
}

// ---------------- host orchestration --------------------------------------
extern "C" void kernel_launch(void* const* d_in, const int* in_sizes, int n_in,
                              void* d_out, int out_size) {
    const float* x_in = (const float*)d_in[0];
    const int* ei = (const int*)d_in[1];
    const int* batch = (const int*)d_in[2];

    const float* gcn_w[4] = {(const float*)d_in[3], (const float*)d_in[7],
                             (const float*)d_in[11], (const float*)d_in[15]};
    const float* gcn_b[4] = {(const float*)d_in[4], (const float*)d_in[8],
                             (const float*)d_in[12], (const float*)d_in[16]};
    const float* bn_g[4] = {(const float*)d_in[5], (const float*)d_in[9],
                            (const float*)d_in[13], (const float*)d_in[17]};
    const float* bn_b[4] = {(const float*)d_in[6], (const float*)d_in[10],
                            (const float*)d_in[14], (const float*)d_in[18]};
    const float* gat_w[2] = {(const float*)d_in[19], (const float*)d_in[23]};
    const float* gat_as[2] = {(const float*)d_in[20], (const float*)d_in[24]};
    const float* gat_ad[2] = {(const float*)d_in[21], (const float*)d_in[25]};
    const float* gat_b[2] = {(const float*)d_in[22], (const float*)d_in[26]};

    float *px, *py, *ph;
    __half *phh, *phgh, *pxh;
    cudaGetSymbolAddress((void**)&px, g_x);
    cudaGetSymbolAddress((void**)&py, g_y);
    cudaGetSymbolAddress((void**)&ph, g_h);
    cudaGetSymbolAddress((void**)&phh, g_hh);
    cudaGetSymbolAddress((void**)&phgh, g_hgh);
    cudaGetSymbolAddress((void**)&pxh, g_xh);

    const int warp_blocks = (NN * 32 + 255) / 256;          // 1 warp/node
    const int warp_blocks2 = (2 * NN * 32 + 255) / 256;     // 2 warps/node
    const int agg_blocks = 148 * 8;
    const dim3 g1((NPAD + 63) / 64, 1);
    const dim3 g2((NPAD + 63) / 64, 2);

    // ---- CSR build ----
    zero_init<<<256, 256>>>();
    hist_k<<<1024, 256>>>(ei + EE, batch);
    scan1<<<NB_SCAN, 1024>>>();
    scan3_dis<<<NB_SCAN, 1024>>>();
    scatter_k<<<1024, 256>>>(ei, ei + EE);

    // ---- layer 0: pre-agg @16, GEMM 16->64 (+bias+stats L0), GAT ----
    pre_agg16_w<<<warp_blocks, 256>>>(x_in, ph);
    gemm_tf32<0, 1><<<g1, 256>>>(ph, gcn_w[0], py, nullptr, NN, 16, 64,
                                 nullptr, nullptr, 0, gcn_b[0], 0, nullptr, nullptr);
    gemm_tf32<1, 2><<<g1, 256>>>(py, gat_w[0], nullptr, phgh, NN, 64, 64,
                                 bn_g[0], bn_b[0], 0, nullptr, 0, gat_as[0], gat_ad[0]);
    gat_agg64_h<<<warp_blocks, 256>>>((const __half2*)phgh, py, gat_b[0],
                                      (__half2*)pxh, bn_g[0], bn_b[0], 0);

    // ---- layer 1: pre-agg @64, GEMM 64->128 (+bias+stats L1) ----
    pre_agg64_h<<<warp_blocks, 256>>>((const __half2*)pxh, ph);
    gemm_tf32<0, 1><<<g2, 256>>>(ph, gcn_w[1], py, nullptr, NN, 64, 128,
                                 nullptr, nullptr, 0, gcn_b[1], 1, nullptr, nullptr);

    // ---- layer 2: GEMM(BN1+lrelu) 128->128 -> half, post-agg(2w), GAT(2w) ----
    gemm_tf32<2, 3><<<g2, 256>>>(py, gcn_w[2], nullptr, phh, NN, 128, 128,
                                 bn_g[1], bn_b[1], 1, nullptr, 0, nullptr, nullptr);
    gcn_agg128_2w<<<warp_blocks2, 256>>>((const __half2*)phh, gcn_b[2], py, 2);
    gemm_tf32<1, 2><<<g2, 256>>>(py, gat_w[1], nullptr, phgh, NN, 128, 128,
                                 bn_g[2], bn_b[2], 2, nullptr, 0, gat_as[1], gat_ad[1]);
    gat_agg128_2w<<<warp_blocks2, 256>>>((const __half2*)phgh, py, gat_b[1],
                                         px, bn_g[2], bn_b[2], 2);

    // ---- layer 3: GEMM 128->64 -> half, post-agg @64 + pooling fused ----
    gemm_tf32<0, 3><<<g1, 256>>>(px, gcn_w[3], nullptr, phh, NN, 128, 64,
                                 nullptr, nullptr, 0, nullptr, 0, nullptr, nullptr);
    gcn_pool_h<<<agg_blocks, 256>>>((const __half2*)phh, gcn_b[3], batch, 3);

    // ---- finalize pooled means (BN3 affine on raw sums) ----
    pool_fin<<<(GG * 64 + 255) / 256, 256>>>((float*)d_out, bn_g[3], bn_b[3]);
}

// round 12
// speedup vs baseline: 1.0687x; 1.0687x over previous
#include <cuda_runtime.h>
#include <cuda_fp16.h>
#include <math.h>
#include <mma.h>

using namespace nvcuda;

#define NN 100000
#define NPAD 100032            /* 1563 * 64 */
#define EE 1600000
#define GG 256
#define NB_SCAN 98             /* ceil(NN/1024) */

// ---------------- scratch (device globals; no allocation allowed) ----------
__device__ float  g_x[NPAD * 128];
__device__ float  g_y[NPAD * 128];
__device__ float  g_h[NPAD * 128];
__device__ __half g_hh[NPAD * 128];     // half gather array: GCN h
__device__ __half g_hgh[NPAD * 128];    // half gather array: GAT hg
__device__ __half g_xh[NPAD * 64];      // half gather array: layer0 GAT output
__device__ int    g_cnt[NN];
__device__ int    g_offs[NN];
__device__ int    g_cursor[NN];
__device__ int    g_csrc[EE];
__device__ float  g_ew[EE];             // per-edge GCN norm dis[src]*dis[dst]
__device__ float  g_dis[NN];
__device__ float  g_an_src[NN * 4];
__device__ float  g_an_dst[NN * 4];
__device__ float  g_bnsum[4][128];
__device__ float  g_bnsq[4][128];
__device__ int    g_bsum[128];
__device__ float  g_pool[GG * 64];
__device__ float  g_pcnt[GG];

__device__ __forceinline__ float lrelu(float v) { return v > 0.f ? v : 0.2f * v; }

__device__ __forceinline__ void bn_affine(int layer, int c, const float* g, const float* b,
                                          float& scv, float& shf) {
    float mean = g_bnsum[layer][c] * (1.f / NN);
    float var = g_bnsq[layer][c] * (1.f / NN) - mean * mean;
    float istd = rsqrtf(var + 1e-5f);
    scv = g[c] * istd;
    shf = b[c] - mean * scv;
}

// ---------------- init / CSR build ----------------------------------------
__global__ void zero_init() {
    int i = blockIdx.x * blockDim.x + threadIdx.x;
    int stride = gridDim.x * blockDim.x;
    for (int t = i; t < NN; t += stride) { g_cnt[t] = 0; g_cursor[t] = 0; }
    for (int t = i; t < GG * 64; t += stride) g_pool[t] = 0.f;
    for (int t = i; t < GG; t += stride) g_pcnt[t] = 0.f;
    for (int t = i; t < 4 * 128; t += stride) { (&g_bnsum[0][0])[t] = 0.f; (&g_bnsq[0][0])[t] = 0.f; }
}

__global__ void hist_k(const int* __restrict__ col, const int* __restrict__ batch) {
    int i = blockIdx.x * blockDim.x + threadIdx.x;
    int stride = gridDim.x * blockDim.x;
    for (int e = i; e < EE; e += stride)
        atomicAdd(&g_cnt[col[e]], 1);
    for (int t = i; t < NN; t += stride)
        atomicAdd(&g_pcnt[batch[t]], 1.f);
}

__global__ void scan1() {
    __shared__ int s[1024];
    int t = threadIdx.x;
    int gi = blockIdx.x * 1024 + t;
    int v = (gi < NN) ? g_cnt[gi] : 0;
    s[t] = v;
    for (int off = 1; off < 1024; off <<= 1) {
        __syncthreads();
        int u = (t >= off) ? s[t - off] : 0;
        __syncthreads();
        s[t] += u;
    }
    if (gi < NN) g_offs[gi] = s[t] - v;
    if (t == 1023) g_bsum[blockIdx.x] = s[1023];
}

__global__ void scan3_dis() {
    __shared__ int sbase;
    int t = threadIdx.x;
    if (t == 0) sbase = 0;
    __syncthreads();
    int p = (t < blockIdx.x) ? g_bsum[t] : 0;
#pragma unroll
    for (int off = 16; off > 0; off >>= 1)
        p += __shfl_xor_sync(0xffffffffu, p, off);
    if ((t & 31) == 0 && p) atomicAdd(&sbase, p);
    __syncthreads();
    int gi = blockIdx.x * 1024 + t;
    if (gi < NN) {
        g_offs[gi] += sbase;
        g_dis[gi] = rsqrtf((float)(g_cnt[gi] + 1));
    }
}

__global__ void scatter_k(const int* __restrict__ row, const int* __restrict__ col) {
    int i = blockIdx.x * blockDim.x + threadIdx.x;
    for (int e = i; e < EE; e += gridDim.x * blockDim.x) {
        int c = col[e];
        int r = row[e];
        int pos = g_offs[c] + atomicAdd(&g_cursor[c], 1);
        g_csrc[pos] = r;
        g_ew[pos] = g_dis[r] * g_dis[c];
    }
}

// ---------------- GEMM: 3xTF32 WMMA, pre-split tiles -----------------------
#define BM 64
#define BN 64
#define BK 32

template <int TRANS, int EPI>
__global__ void gemm_tf32(const float* __restrict__ A, const float* __restrict__ W,
                          float* __restrict__ out, __half* __restrict__ out_h,
                          int n, int din, int dout,
                          const float* __restrict__ bng, const float* __restrict__ bnb,
                          int alayer,
                          const float* __restrict__ bias, int slayer,
                          const float* __restrict__ av_src, const float* __restrict__ av_dst) {
    __shared__ float As[2][BM][BK + 8];
    __shared__ float Bs[2][BK][BN + 8];
    __shared__ float sc_s[128], sh_s[128];
    int tid = threadIdx.x;
    int warp = tid >> 5;
    int wr = warp >> 1;
    int wc = warp & 1;
    int row0 = blockIdx.x * BM;
    int col0 = blockIdx.y * BN;

    if (TRANS > 0) {
        for (int t = tid; t < din; t += 256) {
            float scv, shf;
            bn_affine(alayer, t, bng, bnb, scv, shf);
            sc_s[t] = scv;
            sh_s[t] = shf;
        }
        __syncthreads();
    }

    wmma::fragment<wmma::accumulator, 16, 16, 8, float> acc[2];
    wmma::fill_fragment(acc[0], 0.f);
    wmma::fill_fragment(acc[1], 0.f);

    for (int k0 = 0; k0 < din; k0 += BK) {
#pragma unroll
        for (int v = tid; v < BM * 8; v += 256) {
            int r = v >> 3;
            int kk = (v & 7) * 4;
            float4 val = make_float4(0.f, 0.f, 0.f, 0.f);
            int grow = row0 + r, gk = k0 + kk;
            if (grow < n && gk < din) {
                val = *(const float4*)(A + (size_t)grow * din + gk);
                if (TRANS > 0) {
                    val.x = val.x * sc_s[gk] + sh_s[gk];
                    val.y = val.y * sc_s[gk + 1] + sh_s[gk + 1];
                    val.z = val.z * sc_s[gk + 2] + sh_s[gk + 2];
                    val.w = val.w * sc_s[gk + 3] + sh_s[gk + 3];
                    if (TRANS == 2) {
                        val.x = lrelu(val.x); val.y = lrelu(val.y);
                        val.z = lrelu(val.z); val.w = lrelu(val.w);
                    }
                }
            }
            float4 hi, lo;
            hi.x = wmma::__float_to_tf32(val.x); lo.x = wmma::__float_to_tf32(val.x - hi.x);
            hi.y = wmma::__float_to_tf32(val.y); lo.y = wmma::__float_to_tf32(val.y - hi.y);
            hi.z = wmma::__float_to_tf32(val.z); lo.z = wmma::__float_to_tf32(val.z - hi.z);
            hi.w = wmma::__float_to_tf32(val.w); lo.w = wmma::__float_to_tf32(val.w - hi.w);
            *(float4*)&As[0][r][kk] = hi;
            *(float4*)&As[1][r][kk] = lo;
        }
#pragma unroll
        for (int v = tid; v < BK * 16; v += 256) {
            int kk = v >> 4;
            int cc = (v & 15) * 4;
            float4 val = make_float4(0.f, 0.f, 0.f, 0.f);
            int gk = k0 + kk;
            if (gk < din)
                val = *(const float4*)(W + (size_t)gk * dout + col0 + cc);
            float4 hi, lo;
            hi.x = wmma::__float_to_tf32(val.x); lo.x = wmma::__float_to_tf32(val.x - hi.x);
            hi.y = wmma::__float_to_tf32(val.y); lo.y = wmma::__float_to_tf32(val.y - hi.y);
            hi.z = wmma::__float_to_tf32(val.z); lo.z = wmma::__float_to_tf32(val.z - hi.z);
            hi.w = wmma::__float_to_tf32(val.w); lo.w = wmma::__float_to_tf32(val.w - hi.w);
            *(float4*)&Bs[0][kk][cc] = hi;
            *(float4*)&Bs[1][kk][cc] = lo;
        }
        __syncthreads();

#pragma unroll
        for (int ks = 0; ks < BK; ks += 8) {
            wmma::fragment<wmma::matrix_a, 16, 16, 8, wmma::precision::tf32, wmma::row_major> a_hi, a_lo;
            wmma::load_matrix_sync(a_hi, &As[0][wr * 16][ks], BK + 8);
            wmma::load_matrix_sync(a_lo, &As[1][wr * 16][ks], BK + 8);
#pragma unroll
            for (int c = 0; c < 2; c++) {
                wmma::fragment<wmma::matrix_b, 16, 16, 8, wmma::precision::tf32, wmma::row_major> b_hi, b_lo;
                wmma::load_matrix_sync(b_hi, &Bs[0][ks][wc * 32 + c * 16], BN + 8);
                wmma::load_matrix_sync(b_lo, &Bs[1][ks][wc * 32 + c * 16], BN + 8);
                wmma::mma_sync(acc[c], a_hi, b_hi, acc[c]);
                wmma::mma_sync(acc[c], a_lo, b_hi, acc[c]);
                wmma::mma_sync(acc[c], a_hi, b_lo, acc[c]);
            }
        }
        __syncthreads();
    }

    float* buf = &As[0][0][0];
    const int LDB = 72;
#pragma unroll
    for (int c = 0; c < 2; c++)
        wmma::store_matrix_sync(buf + (wr * 16) * LDB + wc * 32 + c * 16,
                                acc[c], LDB, wmma::mem_row_major);
    __syncthreads();

    if (EPI == 1) {
        int col = tid & 63;
        int part = tid >> 6;
        int gcol = col0 + col;
        float bv = bias[gcol];
        float s = 0.f, q = 0.f;
#pragma unroll
        for (int r = part * 16; r < part * 16 + 16; r++) {
            float v = buf[r * LDB + col] + bv;
            int grow = row0 + r;
            out[(size_t)grow * dout + gcol] = v;
            if (grow < n) { s += v; q += v * v; }
        }
        __shared__ float cS[64], cQ[64];
        if (tid < 64) { cS[tid] = 0.f; cQ[tid] = 0.f; }
        __syncthreads();
        atomicAdd(&cS[col], s);
        atomicAdd(&cQ[col], q);
        __syncthreads();
        if (tid < 64) {
            atomicAdd(&g_bnsum[slayer][col0 + tid], cS[tid]);
            atomicAdd(&g_bnsq[slayer][col0 + tid], cQ[tid]);
        }
    } else {
        __half2* oh = (__half2*)out_h;
        int d2 = dout >> 1;
#pragma unroll
        for (int idx = tid; idx < 64 * 32; idx += 256) {
            int r = idx >> 5, c2 = idx & 31;
            float v0 = buf[r * LDB + 2 * c2];
            float v1 = buf[r * LDB + 2 * c2 + 1];
            oh[(size_t)(row0 + r) * d2 + (col0 >> 1) + c2] = __floats2half2_rn(v0, v1);
        }
        if (EPI == 2) {
            int row = tid & 63;
            int part = tid >> 6;
            int c0 = part * 16;
            int C = dout >> 2;
            int hh = (col0 + c0) / C;
            float s1 = 0.f, s2 = 0.f;
#pragma unroll
            for (int c = c0; c < c0 + 16; c++) {
                float v = buf[row * LDB + c];
                s1 += v * av_src[col0 + c];
                s2 += v * av_dst[col0 + c];
            }
            __shared__ float sA[64][4], sD[64][4];
            sA[tid >> 2][tid & 3] = 0.f;
            sD[tid >> 2][tid & 3] = 0.f;
            __syncthreads();
            atomicAdd(&sA[row][hh], s1);
            atomicAdd(&sD[row][hh], s2);
            __syncthreads();
            int hlo = col0 / C;
            int hcnt = 64 / C;
            if (tid < 64 * hcnt) {
                int r = tid / hcnt, k = tid % hcnt;
                int grow = row0 + r;
                if (grow < n) {
                    g_an_src[grow * 4 + hlo + k] = sA[r][hlo + k];
                    g_an_dst[grow * 4 + hlo + k] = sD[r][hlo + k];
                }
            }
        }
    }
}

// ---------------- pre-aggregation @16: warp/node, half-warp/edge ------------
__global__ void pre_agg16_w(const float* __restrict__ x, float* __restrict__ z) {
    int gw = (blockIdx.x * blockDim.x + threadIdx.x) >> 5;
    if (gw >= NN) return;
    int i = gw;
    int lane = threadIdx.x & 31;
    int half = lane >> 4;
    int col = lane & 15;
    float di = g_dis[i];
    float acc = (half == 0) ? x[(size_t)i * 16 + col] * di * di : 0.f;
    int s = g_offs[i], end = s + g_cnt[i];
    int e = s + half;
    for (; e + 2 < end; e += 4) {
        int j0 = g_csrc[e], j1 = g_csrc[e + 2];
        float w0 = g_ew[e], w1 = g_ew[e + 2];
        acc += x[(size_t)j0 * 16 + col] * w0 + x[(size_t)j1 * 16 + col] * w1;
    }
    if (e < end)
        acc += x[(size_t)g_csrc[e] * 16 + col] * g_ew[e];
    acc += __shfl_xor_sync(0xffffffffu, acc, 16);
    if (half == 0)
        z[(size_t)i * 16 + col] = acc;
}

// ---------------- pre-agg @64 (half input), warp/node, 8-way unroll ---------
__global__ void pre_agg64_h(const __half2* __restrict__ x2, float* __restrict__ z) {
    int gw = (blockIdx.x * blockDim.x + threadIdx.x) >> 5;
    int lane = threadIdx.x & 31;
    if (gw >= NN) return;
    int i = gw;
    float di = g_dis[i], ws = di * di;
    float2 hv = __half22float2(x2[(size_t)i * 32 + lane]);
    float a0 = hv.x * ws, a1 = hv.y * ws;
    int e = g_offs[i], end = e + g_cnt[i];
    for (; e + 7 < end; e += 8) {
        int jj[8]; float wwv[8];
#pragma unroll
        for (int u = 0; u < 8; u++) { jj[u] = g_csrc[e + u]; wwv[u] = g_ew[e + u]; }
        float2 vv[8];
#pragma unroll
        for (int u = 0; u < 8; u++)
            vv[u] = __half22float2(x2[(size_t)jj[u] * 32 + lane]);
#pragma unroll
        for (int u = 0; u < 8; u++) {
            a0 += vv[u].x * wwv[u];
            a1 += vv[u].y * wwv[u];
        }
    }
    for (; e < end; e++) {
        int j = g_csrc[e];
        float w = g_ew[e];
        float2 v = __half22float2(x2[(size_t)j * 32 + lane]);
        a0 += v.x * w;
        a1 += v.y * w;
    }
    *(float2*)&z[(size_t)i * 64 + 2 * lane] = make_float2(a0, a1);
}

// ---------------- GCN post-agg @128: warp/node, 8-way unroll + stats --------
__global__ void gcn_agg128_h(const __half2* __restrict__ h2, const float* __restrict__ bias,
                             float* __restrict__ y, int layer) {
    __shared__ float sS[128], sQ[128];
    int tid = threadIdx.x;
    for (int t = tid; t < 128; t += blockDim.x) { sS[t] = 0.f; sQ[t] = 0.f; }
    __syncthreads();
    int lane = tid & 31;
    int gw = (blockIdx.x * blockDim.x + tid) >> 5;
    int nw = (gridDim.x * blockDim.x) >> 5;
    float b0[2], b1[2];
#pragma unroll
    for (int cc = 0; cc < 2; cc++) {
        int col = cc * 64 + 2 * lane;
        b0[cc] = bias[col]; b1[cc] = bias[col + 1];
    }
    float s0[2] = {0.f, 0.f}, s1[2] = {0.f, 0.f}, q0[2] = {0.f, 0.f}, q1[2] = {0.f, 0.f};

    for (int i = gw; i < NN; i += nw) {
        float di = g_dis[i];
        float ws = di * di;
        float a0[2], a1[2];
#pragma unroll
        for (int cc = 0; cc < 2; cc++) {
            float2 v = __half22float2(h2[(size_t)i * 64 + cc * 32 + lane]);
            a0[cc] = v.x * ws; a1[cc] = v.y * ws;
        }
        int e = g_offs[i];
        int end = e + g_cnt[i];
        for (; e + 7 < end; e += 8) {
            int jj[8]; float wwv[8];
#pragma unroll
            for (int u = 0; u < 8; u++) { jj[u] = g_csrc[e + u]; wwv[u] = g_ew[e + u]; }
#pragma unroll
            for (int cc = 0; cc < 2; cc++) {
                float2 vv[8];
#pragma unroll
                for (int u = 0; u < 8; u++)
                    vv[u] = __half22float2(h2[(size_t)jj[u] * 64 + cc * 32 + lane]);
#pragma unroll
                for (int u = 0; u < 8; u++) {
                    a0[cc] += vv[u].x * wwv[u];
                    a1[cc] += vv[u].y * wwv[u];
                }
            }
        }
        for (; e < end; e++) {
            int j = g_csrc[e];
            float w = g_ew[e];
#pragma unroll
            for (int cc = 0; cc < 2; cc++) {
                float2 v = __half22float2(h2[(size_t)j * 64 + cc * 32 + lane]);
                a0[cc] += v.x * w;
                a1[cc] += v.y * w;
            }
        }
#pragma unroll
        for (int cc = 0; cc < 2; cc++) {
            float v0 = a0[cc] + b0[cc];
            float v1 = a1[cc] + b1[cc];
            int col = cc * 64 + 2 * lane;
            *(float2*)&y[(size_t)i * 128 + col] = make_float2(v0, v1);
            s0[cc] += v0; q0[cc] += v0 * v0;
            s1[cc] += v1; q1[cc] += v1 * v1;
        }
    }
#pragma unroll
    for (int cc = 0; cc < 2; cc++) {
        int col = cc * 64 + 2 * lane;
        atomicAdd(&sS[col], s0[cc]);
        atomicAdd(&sQ[col], q0[cc]);
        atomicAdd(&sS[col + 1], s1[cc]);
        atomicAdd(&sQ[col + 1], q1[cc]);
    }
    __syncthreads();
    for (int t = tid; t < 128; t += blockDim.x) {
        atomicAdd(&g_bnsum[layer][t], sS[t]);
        atomicAdd(&g_bnsq[layer][t], sQ[t]);
    }
}

// ---------------- GCN post-agg @64 fused with pooling, 8-way unroll ---------
__global__ void gcn_pool_h(const __half2* __restrict__ h2, const float* __restrict__ bias,
                           const int* __restrict__ batch, int layer) {
    __shared__ float sS[64], sQ[64];
    int tid = threadIdx.x;
    for (int t = tid; t < 64; t += blockDim.x) { sS[t] = 0.f; sQ[t] = 0.f; }
    __syncthreads();
    int lane = tid & 31;
    int gw = (blockIdx.x * blockDim.x + tid) >> 5;
    int nw = (gridDim.x * blockDim.x) >> 5;
    int col = 2 * lane;
    float b0 = bias[col], b1 = bias[col + 1];
    float s0 = 0.f, s1 = 0.f, q0 = 0.f, q1 = 0.f;

    for (int i = gw; i < NN; i += nw) {
        float di = g_dis[i];
        float ws = di * di;
        float2 hv = __half22float2(h2[(size_t)i * 32 + lane]);
        float a0 = hv.x * ws, a1 = hv.y * ws;
        int e = g_offs[i];
        int end = e + g_cnt[i];
        for (; e + 7 < end; e += 8) {
            int jj[8]; float wwv[8];
#pragma unroll
            for (int u = 0; u < 8; u++) { jj[u] = g_csrc[e + u]; wwv[u] = g_ew[e + u]; }
            float2 vv[8];
#pragma unroll
            for (int u = 0; u < 8; u++)
                vv[u] = __half22float2(h2[(size_t)jj[u] * 32 + lane]);
#pragma unroll
            for (int u = 0; u < 8; u++) {
                a0 += vv[u].x * wwv[u];
                a1 += vv[u].y * wwv[u];
            }
        }
        for (; e < end; e++) {
            int j = g_csrc[e];
            float w = g_ew[e];
            float2 v = __half22float2(h2[(size_t)j * 32 + lane]);
            a0 += v.x * w;
            a1 += v.y * w;
        }
        float v0 = a0 + b0;
        float v1 = a1 + b1;
        int gph = batch[i] * 64 + col;
        atomicAdd(&g_pool[gph], v0);
        atomicAdd(&g_pool[gph + 1], v1);
        s0 += v0; q0 += v0 * v0;
        s1 += v1; q1 += v1 * v1;
    }
    atomicAdd(&sS[col], s0);
    atomicAdd(&sQ[col], q0);
    atomicAdd(&sS[col + 1], s1);
    atomicAdd(&sQ[col + 1], q1);
    __syncthreads();
    for (int t = tid; t < 64; t += blockDim.x) {
        atomicAdd(&g_bnsum[layer][t], sS[t]);
        atomicAdd(&g_bnsq[layer][t], sQ[t]);
    }
}

// ---------------- GAT aggregation: lane-parallel logits, 4-way gather -------
// OUTH=1: half2 output; OUTH=0: fp32 output
template <int DOUT, int OUTH>
__global__ void gat_agg_h(const __half2* __restrict__ hg2, const float* __restrict__ yres,
                          const float* __restrict__ bias,
                          float* __restrict__ xout, __half2* __restrict__ xout_h,
                          const float* __restrict__ bng, const float* __restrict__ bnb,
                          int layer) {
    constexpr int CC = DOUT / 64;
    constexpr int D2 = DOUT / 2;
    constexpr int C = DOUT / 4;
    __shared__ int    sj[8][32];
    __shared__ float4 sq[8][32];
    int gw = (blockIdx.x * blockDim.x + threadIdx.x) >> 5;
    int lane = threadIdx.x & 31;
    int w = threadIdx.x >> 5;
    if (gw >= NN) return;
    int i = gw;
    float4 asi = *(const float4*)&g_an_src[i * 4];
    float4 adi = *(const float4*)&g_an_dst[i * 4];
    float p0 = __expf(lrelu(asi.x + adi.x));
    float p1 = __expf(lrelu(asi.y + adi.y));
    float p2 = __expf(lrelu(asi.z + adi.z));
    float p3 = __expf(lrelu(asi.w + adi.w));
    int hh[CC];
    float a0[CC], a1[CC];
#pragma unroll
    for (int cc = 0; cc < CC; cc++) {
        int col = cc * 64 + 2 * lane;
        hh[cc] = col / C;
        float p = hh[cc] == 0 ? p0 : hh[cc] == 1 ? p1 : hh[cc] == 2 ? p2 : p3;
        float2 hv = __half22float2(hg2[(size_t)i * D2 + cc * 32 + lane]);
        a0[cc] = hv.x * p;
        a1[cc] = hv.y * p;
    }
    float d0 = 0.f, d1 = 0.f, d2 = 0.f, d3 = 0.f;
    int s = g_offs[i], end = s + g_cnt[i];
    for (int base = s; base < end; base += 32) {
        int e = base + lane;
        float4 qv = make_float4(0.f, 0.f, 0.f, 0.f);
        int j = 0;
        if (e < end) {
            j = g_csrc[e];
            float4 aj = *(const float4*)&g_an_src[j * 4];
            qv.x = __expf(lrelu(aj.x + adi.x));
            qv.y = __expf(lrelu(aj.y + adi.y));
            qv.z = __expf(lrelu(aj.z + adi.z));
            qv.w = __expf(lrelu(aj.w + adi.w));
            d0 += qv.x; d1 += qv.y; d2 += qv.z; d3 += qv.w;
        }
        sj[w][lane] = j;
        sq[w][lane] = qv;
        __syncwarp();
        int m = min(32, end - base);
        int k = 0;
        for (; k + 3 < m; k += 4) {
            int jv[4]; float qsel[4];
#pragma unroll
            for (int u = 0; u < 4; u++) jv[u] = sj[w][k + u];
#pragma unroll
            for (int cc = 0; cc < CC; cc++) {
#pragma unroll
                for (int u = 0; u < 4; u++) qsel[u] = ((const float*)&sq[w][k + u])[hh[cc]];
                float2 vv[4];
#pragma unroll
                for (int u = 0; u < 4; u++)
                    vv[u] = __half22float2(hg2[(size_t)jv[u] * D2 + cc * 32 + lane]);
#pragma unroll
                for (int u = 0; u < 4; u++) {
                    a0[cc] += vv[u].x * qsel[u];
                    a1[cc] += vv[u].y * qsel[u];
                }
            }
        }
        for (; k < m; k++) {
            int j0 = sj[w][k];
#pragma unroll
            for (int cc = 0; cc < CC; cc++) {
                float qa = ((const float*)&sq[w][k])[hh[cc]];
                float2 v0 = __half22float2(hg2[(size_t)j0 * D2 + cc * 32 + lane]);
                a0[cc] += v0.x * qa;
                a1[cc] += v0.y * qa;
            }
        }
        __syncwarp();
    }
#pragma unroll
    for (int off = 16; off > 0; off >>= 1) {
        d0 += __shfl_xor_sync(0xffffffffu, d0, off);
        d1 += __shfl_xor_sync(0xffffffffu, d1, off);
        d2 += __shfl_xor_sync(0xffffffffu, d2, off);
        d3 += __shfl_xor_sync(0xffffffffu, d3, off);
    }
    d0 += p0; d1 += p1; d2 += p2; d3 += p3;
#pragma unroll
    for (int cc = 0; cc < CC; cc++) {
        float d = hh[cc] == 0 ? d0 : hh[cc] == 1 ? d1 : hh[cc] == 2 ? d2 : d3;
        int col = cc * 64 + 2 * lane;
        float sc0, sf0, sc1, sf1;
        bn_affine(layer, col, bng, bnb, sc0, sf0);
        bn_affine(layer, col + 1, bng, bnb, sc1, sf1);
        float2 rv = *(const float2*)&yres[(size_t)i * DOUT + col];
        float v0 = lrelu(a0[cc] / d + bias[col] + rv.x * sc0 + sf0);
        float v1 = lrelu(a1[cc] / d + bias[col + 1] + rv.y * sc1 + sf1);
        if (OUTH)
            xout_h[(size_t)i * D2 + cc * 32 + lane] = __floats2half2_rn(v0, v1);
        else
            *(float2*)&xout[(size_t)i * DOUT + col] = make_float2(v0, v1);
    }
}

// ---------------- pooling finalize ------------------------------------------
__global__ void pool_fin(float* __restrict__ out,
                         const float* __restrict__ bng, const float* __restrict__ bnb) {
    int i = blockIdx.x * blockDim.x + threadIdx.x;
    if (i < GG * 64) {
        int g = i >> 6, c = i & 63;
        float scv, shf;
        bn_affine(3, c, bng, bnb, scv, shf);
        float cnt = g_pcnt[g];
        out[i] = (g_pool[i] * scv + shf * cnt) / fmaxf(cnt, 1.f);
    }
}

// ---------------- host orchestration --------------------------------------
extern "C" void kernel_launch(void* const* d_in, const int* in_sizes, int n_in,
                              void* d_out, int out_size) {
    const float* x_in = (const float*)d_in[0];
    const int* ei = (const int*)d_in[1];
    const int* batch = (const int*)d_in[2];

    const float* gcn_w[4] = {(const float*)d_in[3], (const float*)d_in[7],
                             (const float*)d_in[11], (const float*)d_in[15]};
    const float* gcn_b[4] = {(const float*)d_in[4], (const float*)d_in[8],
                             (const float*)d_in[12], (const float*)d_in[16]};
    const float* bn_g[4] = {(const float*)d_in[5], (const float*)d_in[9],
                            (const float*)d_in[13], (const float*)d_in[17]};
    const float* bn_b[4] = {(const float*)d_in[6], (const float*)d_in[10],
                            (const float*)d_in[14], (const float*)d_in[18]};
    const float* gat_w[2] = {(const float*)d_in[19], (const float*)d_in[23]};
    const float* gat_as[2] = {(const float*)d_in[20], (const float*)d_in[24]};
    const float* gat_ad[2] = {(const float*)d_in[21], (const float*)d_in[25]};
    const float* gat_b[2] = {(const float*)d_in[22], (const float*)d_in[26]};

    float *px, *py, *ph;
    __half *phh, *phgh, *pxh;
    cudaGetSymbolAddress((void**)&px, g_x);
    cudaGetSymbolAddress((void**)&py, g_y);
    cudaGetSymbolAddress((void**)&ph, g_h);
    cudaGetSymbolAddress((void**)&phh, g_hh);
    cudaGetSymbolAddress((void**)&phgh, g_hgh);
    cudaGetSymbolAddress((void**)&pxh, g_xh);

    const int warp_blocks = (NN * 32 + 255) / 256;
    const int agg_blocks = 148 * 8;
    const dim3 g1((NPAD + 63) / 64, 1);
    const dim3 g2((NPAD + 63) / 64, 2);

    // ---- CSR build ----
    zero_init<<<256, 256>>>();
    hist_k<<<1024, 256>>>(ei + EE, batch);
    scan1<<<NB_SCAN, 1024>>>();
    scan3_dis<<<NB_SCAN, 1024>>>();
    scatter_k<<<1024, 256>>>(ei, ei + EE);

    // ---- layer 0: pre-agg @16, GEMM 16->64 (+bias+stats L0), GAT ----
    pre_agg16_w<<<warp_blocks, 256>>>(x_in, ph);
    gemm_tf32<0, 1><<<g1, 256>>>(ph, gcn_w[0], py, nullptr, NN, 16, 64,
                                 nullptr, nullptr, 0, gcn_b[0], 0, nullptr, nullptr);
    gemm_tf32<1, 2><<<g1, 256>>>(py, gat_w[0], nullptr, phgh, NN, 64, 64,
                                 bn_g[0], bn_b[0], 0, nullptr, 0, gat_as[0], gat_ad[0]);
    gat_agg_h<64, 1><<<warp_blocks, 256>>>((const __half2*)phgh, py, gat_b[0],
                                           nullptr, (__half2*)pxh,
                                           bn_g[0], bn_b[0], 0);

    // ---- layer 1: pre-agg @64, GEMM 64->128 (+bias+stats L1) ----
    pre_agg64_h<<<warp_blocks, 256>>>((const __half2*)pxh, ph);
    gemm_tf32<0, 1><<<g2, 256>>>(ph, gcn_w[1], py, nullptr, NN, 64, 128,
                                 nullptr, nullptr, 0, gcn_b[1], 1, nullptr, nullptr);

    // ---- layer 2: GEMM(BN1+lrelu) 128->128 -> half, post-agg, GAT ----
    gemm_tf32<2, 3><<<g2, 256>>>(py, gcn_w[2], nullptr, phh, NN, 128, 128,
                                 bn_g[1], bn_b[1], 1, nullptr, 0, nullptr, nullptr);
    gcn_agg128_h<<<agg_blocks, 256>>>((const __half2*)phh, gcn_b[2], py, 2);
    gemm_tf32<1, 2><<<g2, 256>>>(py, gat_w[1], nullptr, phgh, NN, 128, 128,
                                 bn_g[2], bn_b[2], 2, nullptr, 0, gat_as[1], gat_ad[1]);
    gat_agg_h<128, 0><<<warp_blocks, 256>>>((const __half2*)phgh, py, gat_b[1],
                                            px, nullptr, bn_g[2], bn_b[2], 2);

    // ---- layer 3: GEMM 128->64 -> half, post-agg @64 + pooling fused ----
    gemm_tf32<0, 3><<<g1, 256>>>(px, gcn_w[3], nullptr, phh, NN, 128, 64,
                                 nullptr, nullptr, 0, nullptr, 0, nullptr, nullptr);
    gcn_pool_h<<<agg_blocks, 256>>>((const __half2*)phh, gcn_b[3], batch, 3);

    // ---- finalize pooled means (BN3 affine on raw sums) ----
    pool_fin<<<(GG * 64 + 255) / 256, 256>>>((float*)d_out, bn_g[3], bn_b[3]);
}

// round 13
// speedup vs baseline: 1.5437x; 1.4445x over previous
#include <cuda_runtime.h>
#include <cuda_fp16.h>
#include <math.h>
#include <mma.h>

using namespace nvcuda;

#define NN 100000
#define NPAD 100032            /* 1563 * 64 */
#define EE 1600000
#define GG 256
#define NB_SCAN 98             /* ceil(NN/1024) */

// ---------------- scratch (device globals; no allocation allowed) ----------
__device__ float  g_x[NPAD * 128];
__device__ float  g_y[NPAD * 128];
__device__ float  g_h[NPAD * 128];
__device__ __half g_hh[NPAD * 128];     // half gather array: GCN h
__device__ __half g_hgh[NPAD * 128];    // half gather array: GAT hg
__device__ __half g_xh[NPAD * 64];      // half gather array: layer0 GAT output
__device__ int    g_cnt[NN];
__device__ int    g_offs[NN];
__device__ int    g_cursor[NN];
__device__ int    g_csrc[EE];
__device__ float  g_ew[EE];             // per-edge GCN norm dis[src]*dis[dst]
__device__ float  g_dis[NN];
__device__ float  g_an_src[NN * 4];
__device__ float  g_an_dst[NN * 4];
__device__ float  g_bnsum[4][128];
__device__ float  g_bnsq[4][128];
__device__ int    g_bsum[128];
__device__ float  g_pool[GG * 64];
__device__ float  g_pcnt[GG];

__device__ __forceinline__ float lrelu(float v) { return v > 0.f ? v : 0.2f * v; }

__device__ __forceinline__ void bn_affine(int layer, int c, const float* g, const float* b,
                                          float& scv, float& shf) {
    float mean = g_bnsum[layer][c] * (1.f / NN);
    float var = g_bnsq[layer][c] * (1.f / NN) - mean * mean;
    float istd = rsqrtf(var + 1e-5f);
    scv = g[c] * istd;
    shf = b[c] - mean * scv;
}

// ---------------- init / CSR build ----------------------------------------
__global__ void zero_init() {
    int i = blockIdx.x * blockDim.x + threadIdx.x;
    int stride = gridDim.x * blockDim.x;
    for (int t = i; t < NN; t += stride) { g_cnt[t] = 0; g_cursor[t] = 0; }
    for (int t = i; t < GG * 64; t += stride) g_pool[t] = 0.f;
    for (int t = i; t < GG; t += stride) g_pcnt[t] = 0.f;
    for (int t = i; t < 4 * 128; t += stride) { (&g_bnsum[0][0])[t] = 0.f; (&g_bnsq[0][0])[t] = 0.f; }
}

__global__ void hist_k(const int* __restrict__ col, const int* __restrict__ batch) {
    int i = blockIdx.x * blockDim.x + threadIdx.x;
    int stride = gridDim.x * blockDim.x;
    for (int e = i; e < EE; e += stride)
        atomicAdd(&g_cnt[col[e]], 1);
    for (int t = i; t < NN; t += stride)
        atomicAdd(&g_pcnt[batch[t]], 1.f);
}

__global__ void scan1() {
    __shared__ int s[1024];
    int t = threadIdx.x;
    int gi = blockIdx.x * 1024 + t;
    int v = (gi < NN) ? g_cnt[gi] : 0;
    s[t] = v;
    for (int off = 1; off < 1024; off <<= 1) {
        __syncthreads();
        int u = (t >= off) ? s[t - off] : 0;
        __syncthreads();
        s[t] += u;
    }
    if (gi < NN) g_offs[gi] = s[t] - v;
    if (t == 1023) g_bsum[blockIdx.x] = s[1023];
}

__global__ void scan3_dis() {
    __shared__ int sbase;
    int t = threadIdx.x;
    if (t == 0) sbase = 0;
    __syncthreads();
    int p = (t < blockIdx.x) ? g_bsum[t] : 0;
#pragma unroll
    for (int off = 16; off > 0; off >>= 1)
        p += __shfl_xor_sync(0xffffffffu, p, off);
    if ((t & 31) == 0 && p) atomicAdd(&sbase, p);
    __syncthreads();
    int gi = blockIdx.x * 1024 + t;
    if (gi < NN) {
        g_offs[gi] += sbase;
        g_dis[gi] = rsqrtf((float)(g_cnt[gi] + 1));
    }
}

__global__ void scatter_k(const int* __restrict__ row, const int* __restrict__ col) {
    int i = blockIdx.x * blockDim.x + threadIdx.x;
    for (int e = i; e < EE; e += gridDim.x * blockDim.x) {
        int c = col[e];
        int r = row[e];
        int pos = g_offs[c] + atomicAdd(&g_cursor[c], 1);
        g_csrc[pos] = r;
        g_ew[pos] = g_dis[r] * g_dis[c];
    }
}

// ---------------- GEMM: 3xFP16 hi/lo WMMA (m16n16k16) ----------------------
// TRANS: 0 none | 1 A'=A*bn | 2 A'=lrelu(A*bn)
// EPI:   1 fp32 store +bias & BN stats | 2 half store + GAT logits | 3 half store
#define BM 64
#define BN 64
#define BK 32
#define LDA_H 40               /* BK+8 halfs, multiple of 8 */
#define LDB_H 72               /* BN+8 halfs, multiple of 8 */

template <int TRANS, int EPI>
__global__ void gemm_fp16(const float* __restrict__ A, const float* __restrict__ W,
                          float* __restrict__ out, __half* __restrict__ out_h,
                          int n, int din, int dout,
                          const float* __restrict__ bng, const float* __restrict__ bnb,
                          int alayer,
                          const float* __restrict__ bias, int slayer,
                          const float* __restrict__ av_src, const float* __restrict__ av_dst) {
    __shared__ __align__(16) __half As[2][BM][LDA_H];   // hi / lo
    __shared__ __align__(16) __half Bs[2][BK][LDB_H];
    __shared__ float ebuf[BM * 72];                     // fp32 epilogue staging
    __shared__ float sc_s[128], sh_s[128];
    int tid = threadIdx.x;
    int warp = tid >> 5;
    int wr = warp >> 1;
    int wc = warp & 1;
    int row0 = blockIdx.x * BM;
    int col0 = blockIdx.y * BN;

    if (TRANS > 0) {
        for (int t = tid; t < din; t += 256) {
            float scv, shf;
            bn_affine(alayer, t, bng, bnb, scv, shf);
            sc_s[t] = scv;
            sh_s[t] = shf;
        }
        __syncthreads();
    }

    wmma::fragment<wmma::accumulator, 16, 16, 16, float> acc[2];
    wmma::fill_fragment(acc[0], 0.f);
    wmma::fill_fragment(acc[1], 0.f);

    for (int k0 = 0; k0 < din; k0 += BK) {
        // A tile: 64 x 32 (hi/lo halves)
#pragma unroll
        for (int v = tid; v < BM * 8; v += 256) {
            int r = v >> 3;
            int kk = (v & 7) * 4;
            float4 val = make_float4(0.f, 0.f, 0.f, 0.f);
            int grow = row0 + r, gk = k0 + kk;
            if (grow < n && gk < din) {
                val = *(const float4*)(A + (size_t)grow * din + gk);
                if (TRANS > 0) {
                    val.x = val.x * sc_s[gk] + sh_s[gk];
                    val.y = val.y * sc_s[gk + 1] + sh_s[gk + 1];
                    val.z = val.z * sc_s[gk + 2] + sh_s[gk + 2];
                    val.w = val.w * sc_s[gk + 3] + sh_s[gk + 3];
                    if (TRANS == 2) {
                        val.x = lrelu(val.x); val.y = lrelu(val.y);
                        val.z = lrelu(val.z); val.w = lrelu(val.w);
                    }
                }
            }
            __half hx = __float2half_rn(val.x), hy = __float2half_rn(val.y);
            __half hz = __float2half_rn(val.z), hw = __float2half_rn(val.w);
            __half lx = __float2half_rn(val.x - __half2float(hx));
            __half ly = __float2half_rn(val.y - __half2float(hy));
            __half lz = __float2half_rn(val.z - __half2float(hz));
            __half lw = __float2half_rn(val.w - __half2float(hw));
            *(__half2*)&As[0][r][kk] = __halves2half2(hx, hy);
            *(__half2*)&As[0][r][kk + 2] = __halves2half2(hz, hw);
            *(__half2*)&As[1][r][kk] = __halves2half2(lx, ly);
            *(__half2*)&As[1][r][kk + 2] = __halves2half2(lz, lw);
        }
        // B tile: 32 x 64 (hi/lo halves)
#pragma unroll
        for (int v = tid; v < BK * 16; v += 256) {
            int kk = v >> 4;
            int cc = (v & 15) * 4;
            float4 val = make_float4(0.f, 0.f, 0.f, 0.f);
            int gk = k0 + kk;
            if (gk < din)
                val = *(const float4*)(W + (size_t)gk * dout + col0 + cc);
            __half hx = __float2half_rn(val.x), hy = __float2half_rn(val.y);
            __half hz = __float2half_rn(val.z), hw = __float2half_rn(val.w);
            __half lx = __float2half_rn(val.x - __half2float(hx));
            __half ly = __float2half_rn(val.y - __half2float(hy));
            __half lz = __float2half_rn(val.z - __half2float(hz));
            __half lw = __float2half_rn(val.w - __half2float(hw));
            *(__half2*)&Bs[0][kk][cc] = __halves2half2(hx, hy);
            *(__half2*)&Bs[0][kk][cc + 2] = __halves2half2(hz, hw);
            *(__half2*)&Bs[1][kk][cc] = __halves2half2(lx, ly);
            *(__half2*)&Bs[1][kk][cc + 2] = __halves2half2(lz, lw);
        }
        __syncthreads();

#pragma unroll
        for (int ks = 0; ks < BK; ks += 16) {
            wmma::fragment<wmma::matrix_a, 16, 16, 16, __half, wmma::row_major> a_hi, a_lo;
            wmma::load_matrix_sync(a_hi, &As[0][wr * 16][ks], LDA_H);
            wmma::load_matrix_sync(a_lo, &As[1][wr * 16][ks], LDA_H);
#pragma unroll
            for (int c = 0; c < 2; c++) {
                wmma::fragment<wmma::matrix_b, 16, 16, 16, __half, wmma::row_major> b_hi, b_lo;
                wmma::load_matrix_sync(b_hi, &Bs[0][ks][wc * 32 + c * 16], LDB_H);
                wmma::load_matrix_sync(b_lo, &Bs[1][ks][wc * 32 + c * 16], LDB_H);
                wmma::mma_sync(acc[c], a_hi, b_hi, acc[c]);
                wmma::mma_sync(acc[c], a_lo, b_hi, acc[c]);
                wmma::mma_sync(acc[c], a_hi, b_lo, acc[c]);
            }
        }
        __syncthreads();
    }

    float* buf = ebuf;
    const int LDB = 72;
#pragma unroll
    for (int c = 0; c < 2; c++)
        wmma::store_matrix_sync(buf + (wr * 16) * LDB + wc * 32 + c * 16,
                                acc[c], LDB, wmma::mem_row_major);
    __syncthreads();

    if (EPI == 1) {
        int col = tid & 63;
        int part = tid >> 6;
        int gcol = col0 + col;
        float bv = bias[gcol];
        float s = 0.f, q = 0.f;
#pragma unroll
        for (int r = part * 16; r < part * 16 + 16; r++) {
            float v = buf[r * LDB + col] + bv;
            int grow = row0 + r;
            out[(size_t)grow * dout + gcol] = v;   // padded scratch: unguarded
            if (grow < n) { s += v; q += v * v; }
        }
        __shared__ float cS[64], cQ[64];
        if (tid < 64) { cS[tid] = 0.f; cQ[tid] = 0.f; }
        __syncthreads();
        atomicAdd(&cS[col], s);
        atomicAdd(&cQ[col], q);
        __syncthreads();
        if (tid < 64) {
            atomicAdd(&g_bnsum[slayer][col0 + tid], cS[tid]);
            atomicAdd(&g_bnsq[slayer][col0 + tid], cQ[tid]);
        }
    } else {
        __half2* oh = (__half2*)out_h;
        int d2 = dout >> 1;
#pragma unroll
        for (int idx = tid; idx < 64 * 32; idx += 256) {
            int r = idx >> 5, c2 = idx & 31;
            float v0 = buf[r * LDB + 2 * c2];
            float v1 = buf[r * LDB + 2 * c2 + 1];
            oh[(size_t)(row0 + r) * d2 + (col0 >> 1) + c2] = __floats2half2_rn(v0, v1);
        }
        if (EPI == 2) {
            int row = tid & 63;
            int part = tid >> 6;
            int c0 = part * 16;
            int C = dout >> 2;
            int hh = (col0 + c0) / C;
            float s1 = 0.f, s2 = 0.f;
#pragma unroll
            for (int c = c0; c < c0 + 16; c++) {
                float v = buf[row * LDB + c];
                s1 += v * av_src[col0 + c];
                s2 += v * av_dst[col0 + c];
            }
            __shared__ float sA[64][4], sD[64][4];
            sA[tid >> 2][tid & 3] = 0.f;
            sD[tid >> 2][tid & 3] = 0.f;
            __syncthreads();
            atomicAdd(&sA[row][hh], s1);
            atomicAdd(&sD[row][hh], s2);
            __syncthreads();
            int hlo = col0 / C;
            int hcnt = 64 / C;
            if (tid < 64 * hcnt) {
                int r = tid / hcnt, k = tid % hcnt;
                int grow = row0 + r;
                if (grow < n) {
                    g_an_src[grow * 4 + hlo + k] = sA[r][hlo + k];
                    g_an_dst[grow * 4 + hlo + k] = sD[r][hlo + k];
                }
            }
        }
    }
}

// ---------------- pre-aggregation @16: warp/node, half-warp/edge ------------
__global__ void pre_agg16_w(const float* __restrict__ x, float* __restrict__ z) {
    int gw = (blockIdx.x * blockDim.x + threadIdx.x) >> 5;
    if (gw >= NN) return;
    int i = gw;
    int lane = threadIdx.x & 31;
    int half = lane >> 4;
    int col = lane & 15;
    float di = g_dis[i];
    float acc = (half == 0) ? x[(size_t)i * 16 + col] * di * di : 0.f;
    int s = g_offs[i], end = s + g_cnt[i];
    int e = s + half;
    for (; e + 2 < end; e += 4) {
        int j0 = g_csrc[e], j1 = g_csrc[e + 2];
        float w0 = g_ew[e], w1 = g_ew[e + 2];
        acc += x[(size_t)j0 * 16 + col] * w0 + x[(size_t)j1 * 16 + col] * w1;
    }
    if (e < end)
        acc += x[(size_t)g_csrc[e] * 16 + col] * g_ew[e];
    acc += __shfl_xor_sync(0xffffffffu, acc, 16);
    if (half == 0)
        z[(size_t)i * 16 + col] = acc;
}

// ---------------- pre-agg @64 (half input), warp/node, 8-way unroll ---------
__global__ void pre_agg64_h(const __half2* __restrict__ x2, float* __restrict__ z) {
    int gw = (blockIdx.x * blockDim.x + threadIdx.x) >> 5;
    int lane = threadIdx.x & 31;
    if (gw >= NN) return;
    int i = gw;
    float di = g_dis[i], ws = di * di;
    float2 hv = __half22float2(x2[(size_t)i * 32 + lane]);
    float a0 = hv.x * ws, a1 = hv.y * ws;
    int e = g_offs[i], end = e + g_cnt[i];
    for (; e + 7 < end; e += 8) {
        int jj[8]; float wwv[8];
#pragma unroll
        for (int u = 0; u < 8; u++) { jj[u] = g_csrc[e + u]; wwv[u] = g_ew[e + u]; }
        float2 vv[8];
#pragma unroll
        for (int u = 0; u < 8; u++)
            vv[u] = __half22float2(x2[(size_t)jj[u] * 32 + lane]);
#pragma unroll
        for (int u = 0; u < 8; u++) {
            a0 += vv[u].x * wwv[u];
            a1 += vv[u].y * wwv[u];
        }
    }
    for (; e < end; e++) {
        int j = g_csrc[e];
        float w = g_ew[e];
        float2 v = __half22float2(x2[(size_t)j * 32 + lane]);
        a0 += v.x * w;
        a1 += v.y * w;
    }
    *(float2*)&z[(size_t)i * 64 + 2 * lane] = make_float2(a0, a1);
}

// ---------------- GCN post-agg @128: warp/node, 8-way unroll + stats --------
__global__ void gcn_agg128_h(const __half2* __restrict__ h2, const float* __restrict__ bias,
                             float* __restrict__ y, int layer) {
    __shared__ float sS[128], sQ[128];
    int tid = threadIdx.x;
    for (int t = tid; t < 128; t += blockDim.x) { sS[t] = 0.f; sQ[t] = 0.f; }
    __syncthreads();
    int lane = tid & 31;
    int gw = (blockIdx.x * blockDim.x + tid) >> 5;
    int nw = (gridDim.x * blockDim.x) >> 5;
    float b0[2], b1[2];
#pragma unroll
    for (int cc = 0; cc < 2; cc++) {
        int col = cc * 64 + 2 * lane;
        b0[cc] = bias[col]; b1[cc] = bias[col + 1];
    }
    float s0[2] = {0.f, 0.f}, s1[2] = {0.f, 0.f}, q0[2] = {0.f, 0.f}, q1[2] = {0.f, 0.f};

    for (int i = gw; i < NN; i += nw) {
        float di = g_dis[i];
        float ws = di * di;
        float a0[2], a1[2];
#pragma unroll
        for (int cc = 0; cc < 2; cc++) {
            float2 v = __half22float2(h2[(size_t)i * 64 + cc * 32 + lane]);
            a0[cc] = v.x * ws; a1[cc] = v.y * ws;
        }
        int e = g_offs[i];
        int end = e + g_cnt[i];
        for (; e + 7 < end; e += 8) {
            int jj[8]; float wwv[8];
#pragma unroll
            for (int u = 0; u < 8; u++) { jj[u] = g_csrc[e + u]; wwv[u] = g_ew[e + u]; }
#pragma unroll
            for (int cc = 0; cc < 2; cc++) {
                float2 vv[8];
#pragma unroll
                for (int u = 0; u < 8; u++)
                    vv[u] = __half22float2(h2[(size_t)jj[u] * 64 + cc * 32 + lane]);
#pragma unroll
                for (int u = 0; u < 8; u++) {
                    a0[cc] += vv[u].x * wwv[u];
                    a1[cc] += vv[u].y * wwv[u];
                }
            }
        }
        for (; e < end; e++) {
            int j = g_csrc[e];
            float w = g_ew[e];
#pragma unroll
            for (int cc = 0; cc < 2; cc++) {
                float2 v = __half22float2(h2[(size_t)j * 64 + cc * 32 + lane]);
                a0[cc] += v.x * w;
                a1[cc] += v.y * w;
            }
        }
#pragma unroll
        for (int cc = 0; cc < 2; cc++) {
            float v0 = a0[cc] + b0[cc];
            float v1 = a1[cc] + b1[cc];
            int col = cc * 64 + 2 * lane;
            *(float2*)&y[(size_t)i * 128 + col] = make_float2(v0, v1);
            s0[cc] += v0; q0[cc] += v0 * v0;
            s1[cc] += v1; q1[cc] += v1 * v1;
        }
    }
#pragma unroll
    for (int cc = 0; cc < 2; cc++) {
        int col = cc * 64 + 2 * lane;
        atomicAdd(&sS[col], s0[cc]);
        atomicAdd(&sQ[col], q0[cc]);
        atomicAdd(&sS[col + 1], s1[cc]);
        atomicAdd(&sQ[col + 1], q1[cc]);
    }
    __syncthreads();
    for (int t = tid; t < 128; t += blockDim.x) {
        atomicAdd(&g_bnsum[layer][t], sS[t]);
        atomicAdd(&g_bnsq[layer][t], sQ[t]);
    }
}

// ---------------- GCN post-agg @64 fused with pooling, 8-way unroll ---------
__global__ void gcn_pool_h(const __half2* __restrict__ h2, const float* __restrict__ bias,
                           const int* __restrict__ batch, int layer) {
    __shared__ float sS[64], sQ[64];
    int tid = threadIdx.x;
    for (int t = tid; t < 64; t += blockDim.x) { sS[t] = 0.f; sQ[t] = 0.f; }
    __syncthreads();
    int lane = tid & 31;
    int gw = (blockIdx.x * blockDim.x + tid) >> 5;
    int nw = (gridDim.x * blockDim.x) >> 5;
    int col = 2 * lane;
    float b0 = bias[col], b1 = bias[col + 1];
    float s0 = 0.f, s1 = 0.f, q0 = 0.f, q1 = 0.f;

    for (int i = gw; i < NN; i += nw) {
        float di = g_dis[i];
        float ws = di * di;
        float2 hv = __half22float2(h2[(size_t)i * 32 + lane]);
        float a0 = hv.x * ws, a1 = hv.y * ws;
        int e = g_offs[i];
        int end = e + g_cnt[i];
        for (; e + 7 < end; e += 8) {
            int jj[8]; float wwv[8];
#pragma unroll
            for (int u = 0; u < 8; u++) { jj[u] = g_csrc[e + u]; wwv[u] = g_ew[e + u]; }
            float2 vv[8];
#pragma unroll
            for (int u = 0; u < 8; u++)
                vv[u] = __half22float2(h2[(size_t)jj[u] * 32 + lane]);
#pragma unroll
            for (int u = 0; u < 8; u++) {
                a0 += vv[u].x * wwv[u];
                a1 += vv[u].y * wwv[u];
            }
        }
        for (; e < end; e++) {
            int j = g_csrc[e];
            float w = g_ew[e];
            float2 v = __half22float2(h2[(size_t)j * 32 + lane]);
            a0 += v.x * w;
            a1 += v.y * w;
        }
        float v0 = a0 + b0;
        float v1 = a1 + b1;
        int gph = batch[i] * 64 + col;
        atomicAdd(&g_pool[gph], v0);
        atomicAdd(&g_pool[gph + 1], v1);
        s0 += v0; q0 += v0 * v0;
        s1 += v1; q1 += v1 * v1;
    }
    atomicAdd(&sS[col], s0);
    atomicAdd(&sQ[col], q0);
    atomicAdd(&sS[col + 1], s1);
    atomicAdd(&sQ[col + 1], q1);
    __syncthreads();
    for (int t = tid; t < 64; t += blockDim.x) {
        atomicAdd(&g_bnsum[layer][t], sS[t]);
        atomicAdd(&g_bnsq[layer][t], sQ[t]);
    }
}

// ---------------- GAT aggregation: lane-parallel logits, 4-way gather -------
template <int DOUT, int OUTH>
__global__ void gat_agg_h(const __half2* __restrict__ hg2, const float* __restrict__ yres,
                          const float* __restrict__ bias,
                          float* __restrict__ xout, __half2* __restrict__ xout_h,
                          const float* __restrict__ bng, const float* __restrict__ bnb,
                          int layer) {
    constexpr int CC = DOUT / 64;
    constexpr int D2 = DOUT / 2;
    constexpr int C = DOUT / 4;
    __shared__ int    sj[8][32];
    __shared__ float4 sq[8][32];
    int gw = (blockIdx.x * blockDim.x + threadIdx.x) >> 5;
    int lane = threadIdx.x & 31;
    int w = threadIdx.x >> 5;
    if (gw >= NN) return;
    int i = gw;
    float4 asi = *(const float4*)&g_an_src[i * 4];
    float4 adi = *(const float4*)&g_an_dst[i * 4];
    float p0 = __expf(lrelu(asi.x + adi.x));
    float p1 = __expf(lrelu(asi.y + adi.y));
    float p2 = __expf(lrelu(asi.z + adi.z));
    float p3 = __expf(lrelu(asi.w + adi.w));
    int hh[CC];
    float a0[CC], a1[CC];
#pragma unroll
    for (int cc = 0; cc < CC; cc++) {
        int col = cc * 64 + 2 * lane;
        hh[cc] = col / C;
        float p = hh[cc] == 0 ? p0 : hh[cc] == 1 ? p1 : hh[cc] == 2 ? p2 : p3;
        float2 hv = __half22float2(hg2[(size_t)i * D2 + cc * 32 + lane]);
        a0[cc] = hv.x * p;
        a1[cc] = hv.y * p;
    }
    float d0 = 0.f, d1 = 0.f, d2 = 0.f, d3 = 0.f;
    int s = g_offs[i], end = s + g_cnt[i];
    for (int base = s; base < end; base += 32) {
        int e = base + lane;
        float4 qv = make_float4(0.f, 0.f, 0.f, 0.f);
        int j = 0;
        if (e < end) {
            j = g_csrc[e];
            float4 aj = *(const float4*)&g_an_src[j * 4];
            qv.x = __expf(lrelu(aj.x + adi.x));
            qv.y = __expf(lrelu(aj.y + adi.y));
            qv.z = __expf(lrelu(aj.z + adi.z));
            qv.w = __expf(lrelu(aj.w + adi.w));
            d0 += qv.x; d1 += qv.y; d2 += qv.z; d3 += qv.w;
        }
        sj[w][lane] = j;
        sq[w][lane] = qv;
        __syncwarp();
        int m = min(32, end - base);
        int k = 0;
        for (; k + 3 < m; k += 4) {
            int jv[4]; float qsel[4];
#pragma unroll
            for (int u = 0; u < 4; u++) jv[u] = sj[w][k + u];
#pragma unroll
            for (int cc = 0; cc < CC; cc++) {
#pragma unroll
                for (int u = 0; u < 4; u++) qsel[u] = ((const float*)&sq[w][k + u])[hh[cc]];
                float2 vv[4];
#pragma unroll
                for (int u = 0; u < 4; u++)
                    vv[u] = __half22float2(hg2[(size_t)jv[u] * D2 + cc * 32 + lane]);
#pragma unroll
                for (int u = 0; u < 4; u++) {
                    a0[cc] += vv[u].x * qsel[u];
                    a1[cc] += vv[u].y * qsel[u];
                }
            }
        }
        for (; k < m; k++) {
            int j0 = sj[w][k];
#pragma unroll
            for (int cc = 0; cc < CC; cc++) {
                float qa = ((const float*)&sq[w][k])[hh[cc]];
                float2 v0 = __half22float2(hg2[(size_t)j0 * D2 + cc * 32 + lane]);
                a0[cc] += v0.x * qa;
                a1[cc] += v0.y * qa;
            }
        }
        __syncwarp();
    }
#pragma unroll
    for (int off = 16; off > 0; off >>= 1) {
        d0 += __shfl_xor_sync(0xffffffffu, d0, off);
        d1 += __shfl_xor_sync(0xffffffffu, d1, off);
        d2 += __shfl_xor_sync(0xffffffffu, d2, off);
        d3 += __shfl_xor_sync(0xffffffffu, d3, off);
    }
    d0 += p0; d1 += p1; d2 += p2; d3 += p3;
#pragma unroll
    for (int cc = 0; cc < CC; cc++) {
        float d = hh[cc] == 0 ? d0 : hh[cc] == 1 ? d1 : hh[cc] == 2 ? d2 : d3;
        int col = cc * 64 + 2 * lane;
        float sc0, sf0, sc1, sf1;
        bn_affine(layer, col, bng, bnb, sc0, sf0);
        bn_affine(layer, col + 1, bng, bnb, sc1, sf1);
        float2 rv = *(const float2*)&yres[(size_t)i * DOUT + col];
        float v0 = lrelu(a0[cc] / d + bias[col] + rv.x * sc0 + sf0);
        float v1 = lrelu(a1[cc] / d + bias[col + 1] + rv.y * sc1 + sf1);
        if (OUTH)
            xout_h[(size_t)i * D2 + cc * 32 + lane] = __floats2half2_rn(v0, v1);
        else
            *(float2*)&xout[(size_t)i * DOUT + col] = make_float2(v0, v1);
    }
}

// ---------------- pooling finalize ------------------------------------------
__global__ void pool_fin(float* __restrict__ out,
                         const float* __restrict__ bng, const float* __restrict__ bnb) {
    int i = blockIdx.x * blockDim.x + threadIdx.x;
    if (i < GG * 64) {
        int g = i >> 6, c = i & 63;
        float scv, shf;
        bn_affine(3, c, bng, bnb, scv, shf);
        float cnt = g_pcnt[g];
        out[i] = (g_pool[i] * scv + shf * cnt) / fmaxf(cnt, 1.f);
    }
}

// ---------------- host orchestration --------------------------------------
extern "C" void kernel_launch(void* const* d_in, const int* in_sizes, int n_in,
                              void* d_out, int out_size) {
    const float* x_in = (const float*)d_in[0];
    const int* ei = (const int*)d_in[1];
    const int* batch = (const int*)d_in[2];

    const float* gcn_w[4] = {(const float*)d_in[3], (const float*)d_in[7],
                             (const float*)d_in[11], (const float*)d_in[15]};
    const float* gcn_b[4] = {(const float*)d_in[4], (const float*)d_in[8],
                             (const float*)d_in[12], (const float*)d_in[16]};
    const float* bn_g[4] = {(const float*)d_in[5], (const float*)d_in[9],
                            (const float*)d_in[13], (const float*)d_in[17]};
    const float* bn_b[4] = {(const float*)d_in[6], (const float*)d_in[10],
                            (const float*)d_in[14], (const float*)d_in[18]};
    const float* gat_w[2] = {(const float*)d_in[19], (const float*)d_in[23]};
    const float* gat_as[2] = {(const float*)d_in[20], (const float*)d_in[24]};
    const float* gat_ad[2] = {(const float*)d_in[21], (const float*)d_in[25]};
    const float* gat_b[2] = {(const float*)d_in[22], (const float*)d_in[26]};

    float *px, *py, *ph;
    __half *phh, *phgh, *pxh;
    cudaGetSymbolAddress((void**)&px, g_x);
    cudaGetSymbolAddress((void**)&py, g_y);
    cudaGetSymbolAddress((void**)&ph, g_h);
    cudaGetSymbolAddress((void**)&phh, g_hh);
    cudaGetSymbolAddress((void**)&phgh, g_hgh);
    cudaGetSymbolAddress((void**)&pxh, g_xh);

    const int warp_blocks = (NN * 32 + 255) / 256;
    const int agg_blocks = 148 * 8;
    const dim3 g1((NPAD + 63) / 64, 1);
    const dim3 g2((NPAD + 63) / 64, 2);

    // ---- CSR build ----
    zero_init<<<256, 256>>>();
    hist_k<<<1024, 256>>>(ei + EE, batch);
    scan1<<<NB_SCAN, 1024>>>();
    scan3_dis<<<NB_SCAN, 1024>>>();
    scatter_k<<<1024, 256>>>(ei, ei + EE);

    // ---- layer 0: pre-agg @16, GEMM 16->64 (+bias+stats L0), GAT ----
    pre_agg16_w<<<warp_blocks, 256>>>(x_in, ph);
    gemm_fp16<0, 1><<<g1, 256>>>(ph, gcn_w[0], py, nullptr, NN, 16, 64,
                                 nullptr, nullptr, 0, gcn_b[0], 0, nullptr, nullptr);
    gemm_fp16<1, 2><<<g1, 256>>>(py, gat_w[0], nullptr, phgh, NN, 64, 64,
                                 bn_g[0], bn_b[0], 0, nullptr, 0, gat_as[0], gat_ad[0]);
    gat_agg_h<64, 1><<<warp_blocks, 256>>>((const __half2*)phgh, py, gat_b[0],
                                           nullptr, (__half2*)pxh,
                                           bn_g[0], bn_b[0], 0);

    // ---- layer 1: pre-agg @64, GEMM 64->128 (+bias+stats L1) ----
    pre_agg64_h<<<warp_blocks, 256>>>((const __half2*)pxh, ph);
    gemm_fp16<0, 1><<<g2, 256>>>(ph, gcn_w[1], py, nullptr, NN, 64, 128,
                                 nullptr, nullptr, 0, gcn_b[1], 1, nullptr, nullptr);

    // ---- layer 2: GEMM(BN1+lrelu) 128->128 -> half, post-agg, GAT ----
    gemm_fp16<2, 3><<<g2, 256>>>(py, gcn_w[2], nullptr, phh, NN, 128, 128,
                                 bn_g[1], bn_b[1], 1, nullptr, 0, nullptr, nullptr);
    gcn_agg128_h<<<agg_blocks, 256>>>((const __half2*)phh, gcn_b[2], py, 2);
    gemm_fp16<1, 2><<<g2, 256>>>(py, gat_w[1], nullptr, phgh, NN, 128, 128,
                                 bn_g[2], bn_b[2], 2, nullptr, 0, gat_as[1], gat_ad[1]);
    gat_agg_h<128, 0><<<warp_blocks, 256>>>((const __half2*)phgh, py, gat_b[1],
                                            px, nullptr, bn_g[2], bn_b[2], 2);

    // ---- layer 3: GEMM 128->64 -> half, post-agg @64 + pooling fused ----
    gemm_fp16<0, 3><<<g1, 256>>>(px, gcn_w[3], nullptr, phh, NN, 128, 64,
                                 nullptr, nullptr, 0, nullptr, 0, nullptr, nullptr);
    gcn_pool_h<<<agg_blocks, 256>>>((const __half2*)phh, gcn_b[3], batch, 3);

    // ---- finalize pooled means (BN3 affine on raw sums) ----
    pool_fin<<<(GG * 64 + 255) / 256, 256>>>((float*)d_out, bn_g[3], bn_b[3]);
}